// round 2
// baseline (speedup 1.0000x reference)
#include <cuda_runtime.h>
#include <math.h>
#include <stdint.h>

#define Bb_ 64
#define Tt_ 4096
#define Dd_ 256
#define Hh_ 256
#define Oo_ 256

// Scratch (device globals: no allocation allowed in kernel_launch)
__device__ float g_xp[(size_t)Tt_ * Bb_ * Hh_];   // (T, B, H)
__device__ float g_hs[(size_t)Bb_ * Tt_ * Hh_];   // (B, T, H)

// ---------------------------------------------------------------------------
// SGEMM: C = A(MxK) @ W(KxN) + bias, K=N=256.
// mode 0: C[row*N + n]           (used for out = hs @ W_hy)
// mode 1: C[((row%T)*B + row/T)*N + n]   (used for xp, stored (T,B,H))
// BM=128, BN=128, BK=8, 256 threads, 8x8 microtile (split-offset frags)
// ---------------------------------------------------------------------------
__global__ void __launch_bounds__(256) sgemm_bias(
    const float* __restrict__ A, const float* __restrict__ W,
    const float* __restrict__ bias, float* __restrict__ C,
    int M, int mode)
{
    const int K = 256, N = 256;
    __shared__ float As[2][8][128];
    __shared__ float Bs[2][8][128];

    int tid = threadIdx.x;
    int rowTile = blockIdx.y;     // M/128
    int colTile = blockIdx.x;     // N/128 = 2

    const float* Ab = A + (size_t)rowTile * 128 * K;
    const float* Wb = W + colTile * 128;

    int aRow = tid >> 1;            // 0..127
    int aCol = (tid & 1) * 4;       // 0 or 4
    int bRow = tid >> 5;            // 0..7
    int bCol = (tid & 31) * 4;      // 0..124

    int ty = tid >> 4;              // 0..15
    int tx = tid & 15;              // 0..15

    float acc[8][8];
#pragma unroll
    for (int i = 0; i < 8; i++)
#pragma unroll
        for (int j = 0; j < 8; j++) acc[i][j] = 0.f;

    // prologue: tile 0
    float4 aReg = *(const float4*)(Ab + (size_t)aRow * K + aCol);
    float4 bReg = *(const float4*)(Wb + (size_t)bRow * N + bCol);
    As[0][aCol + 0][aRow] = aReg.x;
    As[0][aCol + 1][aRow] = aReg.y;
    As[0][aCol + 2][aRow] = aReg.z;
    As[0][aCol + 3][aRow] = aReg.w;
    *(float4*)&Bs[0][bRow][bCol] = bReg;
    __syncthreads();

    const int nK = K / 8;   // 32
    for (int kt = 0; kt < nK; kt++) {
        int cur = kt & 1, nxt = cur ^ 1;
        if (kt + 1 < nK) {
            aReg = *(const float4*)(Ab + (size_t)aRow * K + (kt + 1) * 8 + aCol);
            bReg = *(const float4*)(Wb + (size_t)((kt + 1) * 8 + bRow) * N + bCol);
        }
#pragma unroll
        for (int k = 0; k < 8; k++) {
            float a[8], bv[8];
            *(float4*)&a[0]  = *(const float4*)&As[cur][k][ty * 4];
            *(float4*)&a[4]  = *(const float4*)&As[cur][k][ty * 4 + 64];
            *(float4*)&bv[0] = *(const float4*)&Bs[cur][k][tx * 4];
            *(float4*)&bv[4] = *(const float4*)&Bs[cur][k][tx * 4 + 64];
#pragma unroll
            for (int i = 0; i < 8; i++)
#pragma unroll
                for (int j = 0; j < 8; j++)
                    acc[i][j] = fmaf(a[i], bv[j], acc[i][j]);
        }
        if (kt + 1 < nK) {
            As[nxt][aCol + 0][aRow] = aReg.x;
            As[nxt][aCol + 1][aRow] = aReg.y;
            As[nxt][aCol + 2][aRow] = aReg.z;
            As[nxt][aCol + 3][aRow] = aReg.w;
            *(float4*)&Bs[nxt][bRow][bCol] = bReg;
        }
        __syncthreads();
    }

    // epilogue
#pragma unroll
    for (int i = 0; i < 8; i++) {
        int lm = (i < 4) ? (ty * 4 + i) : (64 + ty * 4 + (i - 4));
        long gm = (long)rowTile * 128 + lm;
        size_t rowOff;
        if (mode == 0) {
            rowOff = (size_t)gm * N;
        } else {
            int t  = (int)(gm % Tt_);
            int bb = (int)(gm / Tt_);
            rowOff = ((size_t)t * Bb_ + bb) * N;
        }
#pragma unroll
        for (int j = 0; j < 8; j++) {
            int ln = (j < 4) ? (tx * 4 + j) : (64 + tx * 4 + (j - 4));
            int gn = colTile * 128 + ln;
            C[rowOff + gn] = acc[i][j] + bias[gn];
        }
    }
}

// ---------------------------------------------------------------------------
// Sequential scan: one CTA per batch chain (64 CTAs, zero cross-CTA sync).
// Thread j owns output column j. W_hh column j: k in [0,160) in registers
// (80 packed f32x2), k in [160,256) in smem (48 u64 pairs, 98 KB).
// Packed fma.rn.f32x2 doubles fp32 MAC throughput.
// ---------------------------------------------------------------------------
#define RP 80   // register k-pairs
#define SP 48   // smem k-pairs
#define SCAN_SMEM (SP * 256 * 8 + 2 * 256 * 4)

#define FMA2(acc, h, w) \
    asm("fma.rn.f32x2 %0, %1, %2, %0;" : "+l"(acc) : "l"(h), "l"(w))

__device__ __forceinline__ unsigned long long pack2(float lo, float hi) {
    unsigned long long v;
    asm("mov.b64 %0, {%1, %2};" : "=l"(v) : "f"(lo), "f"(hi));
    return v;
}
__device__ __forceinline__ float sum2(unsigned long long v) {
    float lo, hi;
    asm("mov.b64 {%0, %1}, %2;" : "=f"(lo), "=f"(hi) : "l"(v));
    return lo + hi;
}

__global__ void __launch_bounds__(256, 1) rnn_scan(
    const float* __restrict__ xp,   // (T, B, H)
    const float* __restrict__ Whh,  // (H, H) [k][j]
    const float* __restrict__ h0,   // (B, H)
    float* __restrict__ hs,         // (B, T, H)
    float* __restrict__ hfin)       // (B, H)
{
    extern __shared__ char smem_raw[];
    unsigned long long* wp = (unsigned long long*)smem_raw;           // [SP][256]
    float* hbuf = (float*)(smem_raw + (size_t)SP * 256 * 8);          // [2][256]

    const int b = blockIdx.x;
    const int j = threadIdx.x;

    // register-resident weights: k pairs [0, RP)
    unsigned long long wr[RP];
#pragma unroll
    for (int p = 0; p < RP; p++) {
        float lo = Whh[(size_t)(2 * p) * Hh_ + j];
        float hi = Whh[(size_t)(2 * p + 1) * Hh_ + j];
        wr[p] = pack2(lo, hi);
    }
    // smem-resident weights: k pairs [RP, 128)
#pragma unroll 4
    for (int p = 0; p < SP; p++) {
        int k = 2 * (RP + p);
        wp[p * 256 + j] = pack2(Whh[(size_t)k * Hh_ + j],
                                Whh[(size_t)(k + 1) * Hh_ + j]);
    }

    hbuf[j] = h0[b * Hh_ + j];
    __syncthreads();

    // xp prefetch pipeline (2 steps ahead)
    float xpc = __ldcs(&xp[((size_t)0 * Bb_ + b) * Hh_ + j]);
    float xpn = __ldcs(&xp[((size_t)1 * Bb_ + b) * Hh_ + j]);

    const size_t hs_base = ((size_t)b * Tt_) * Hh_ + j;
    int pb = 0;
    float hlast = 0.f;

    for (int t = 0; t < Tt_; t++) {
        const ulonglong2* hc2 =
            (const ulonglong2*)(hbuf + pb * 256);   // 64 x 16B, warp-broadcast

        unsigned long long a0 = 0ull, a1 = 0ull, a2 = 0ull, a3 = 0ull;

#pragma unroll
        for (int q = 0; q < RP / 2; q++) {          // k pairs 0..79
            ulonglong2 hv = hc2[q];
            FMA2(a0, hv.x, wr[2 * q]);
            FMA2(a1, hv.y, wr[2 * q + 1]);
        }
#pragma unroll
        for (int q = 0; q < SP / 2; q++) {          // k pairs 80..127
            ulonglong2 hv = hc2[RP / 2 + q];
            FMA2(a2, hv.x, wp[(2 * q) * 256 + j]);
            FMA2(a3, hv.y, wp[(2 * q + 1) * 256 + j]);
        }

        float z = (sum2(a0) + sum2(a1)) + (sum2(a2) + sum2(a3)) + xpc;
        float h = tanhf(z);

        hbuf[(pb ^ 1) * 256 + j] = h;
        hs[hs_base + (size_t)t * Hh_] = h;

        xpc = xpn;
        if (t + 2 < Tt_)
            xpn = __ldcs(&xp[((size_t)(t + 2) * Bb_ + b) * Hh_ + j]);

        hlast = h;
        __syncthreads();
        pb ^= 1;
    }

    hfin[b * Hh_ + j] = hlast;
}

// ---------------------------------------------------------------------------
// Launch
// ---------------------------------------------------------------------------
extern "C" void kernel_launch(void* const* d_in, const int* in_sizes, int n_in,
                              void* d_out, int out_size)
{
    const float* x    = (const float*)d_in[0];  // (B,T,D)
    const float* h0   = (const float*)d_in[1];  // (B,H)
    const float* W_xh = (const float*)d_in[2];  // (D,H)
    const float* W_hh = (const float*)d_in[3];  // (H,H)
    const float* b_h  = (const float*)d_in[4];  // (H)
    const float* W_hy = (const float*)d_in[5];  // (H,O)
    const float* b_y  = (const float*)d_in[6];  // (O)

    float* out  = (float*)d_out;                           // (B,T,O)
    float* hfin = out + (size_t)Bb_ * Tt_ * Oo_;           // (B,H)

    void* xp_ptr = nullptr;
    void* hs_ptr = nullptr;
    cudaGetSymbolAddress(&xp_ptr, g_xp);
    cudaGetSymbolAddress(&hs_ptr, g_hs);

    cudaFuncSetAttribute(rnn_scan,
                         cudaFuncAttributeMaxDynamicSharedMemorySize,
                         SCAN_SMEM);

    const int M = Bb_ * Tt_;            // 262144 rows
    dim3 gemmGrid(2, M / 128);

    // 1) xp = x @ W_xh + b_h   -> (T,B,H)
    sgemm_bias<<<gemmGrid, 256>>>(x, W_xh, b_h, (float*)xp_ptr, M, 1);

    // 2) sequential scan -> hs (B,T,H), h_final
    rnn_scan<<<Bb_, 256, SCAN_SMEM>>>((const float*)xp_ptr, W_hh, h0,
                                      (float*)hs_ptr, hfin);

    // 3) out = hs @ W_hy + b_y -> (B,T,O)
    sgemm_bias<<<gemmGrid, 256>>>((const float*)hs_ptr, W_hy, b_y, out, M, 0);
}